// round 1
// baseline (speedup 1.0000x reference)
#include <cuda_runtime.h>

#define EMBED 1024
#define HEADS 16
#define HDIM  64
#define BATCH 2
#define SEQ   2048
#define MTOT  (BATCH*SEQ)   // 4096

// Scratch (static device globals: allocation-free, graph-capture safe)
__device__ float g_Q[(size_t)BATCH*HEADS*SEQ*HDIM];   // [B,H,S,D]
__device__ float g_K[(size_t)BATCH*HEADS*SEQ*HDIM];
__device__ float g_V[(size_t)BATCH*HEADS*SEQ*HDIM];
__device__ float g_A[(size_t)MTOT*EMBED];             // attn out, [B,S,E]

// ---------------------------------------------------------------------------
// SGEMM: C[M=4096, N=1024] = A[M,K=1024] @ W[K,N] + bias[N]
// 128x128 tile, BK=16, 256 threads, 8x8 per-thread, double-buffered smem.
// SPLIT=1: scatter C into [B,H,S,D] layout (head split). csel picks dest.
// ---------------------------------------------------------------------------
template<int SPLIT>
__global__ void __launch_bounds__(256, 2)
sgemm_bias(const float* __restrict__ Aext, const float* __restrict__ W,
           const float* __restrict__ bias, float* __restrict__ Cext,
           int asel, int csel)
{
    const int K = EMBED, N = EMBED;
    const float* A = asel ? g_A : Aext;
    float* C;
    switch (csel) {
        case 1: C = g_Q; break;
        case 2: C = g_K; break;
        case 3: C = g_V; break;
        default: C = Cext; break;
    }

    __shared__ float As[2][16][132];   // transposed A tile: As[k][m]
    __shared__ float Bs[2][16][128];   // Bs[k][n]

    const int tid = threadIdx.x;
    const int bm = blockIdx.y * 128;
    const int bn = blockIdx.x * 128;

    const int arow = tid >> 2;         // 0..63
    const int ak   = (tid & 3) * 4;    // k offset 0,4,8,12
    const int brow = tid >> 5;         // 0..7
    const int bcol = (tid & 31) * 4;   // 0..124

    const int rm = (tid >> 4) << 3;    // 0..120
    const int rn = (tid & 15) << 3;    // 0..120

    float acc[8][8];
    #pragma unroll
    for (int i = 0; i < 8; i++)
        #pragma unroll
        for (int j = 0; j < 8; j++) acc[i][j] = 0.f;

    // prologue: tile 0 -> buffer 0
    {
        const float* Ap = A + (size_t)(bm + arow) * K + ak;
        #pragma unroll
        for (int i = 0; i < 2; i++) {
            float4 v = *(const float4*)(Ap + (size_t)i * 64 * K);
            int row = arow + i * 64;
            As[0][ak+0][row] = v.x; As[0][ak+1][row] = v.y;
            As[0][ak+2][row] = v.z; As[0][ak+3][row] = v.w;
        }
        const float* Bp = W + (size_t)brow * N + bn + bcol;
        #pragma unroll
        for (int i = 0; i < 2; i++)
            *(float4*)&Bs[0][brow + i*8][bcol] = *(const float4*)(Bp + (size_t)i * 8 * N);
    }
    __syncthreads();

    int buf = 0;
    for (int kt = 0; kt < K/16; kt++) {
        float4 pa[2], pb[2];
        const bool more = (kt + 1 < K/16);
        if (more) {
            const float* Ap = A + (size_t)(bm + arow) * K + (kt+1)*16 + ak;
            pa[0] = *(const float4*)(Ap);
            pa[1] = *(const float4*)(Ap + (size_t)64 * K);
            const float* Bp = W + (size_t)((kt+1)*16 + brow) * N + bn + bcol;
            pb[0] = *(const float4*)(Bp);
            pb[1] = *(const float4*)(Bp + (size_t)8 * N);
        }
        #pragma unroll
        for (int k = 0; k < 16; k++) {
            float a[8], b[8];
            *(float4*)&a[0] = *(const float4*)&As[buf][k][rm];
            *(float4*)&a[4] = *(const float4*)&As[buf][k][rm+4];
            *(float4*)&b[0] = *(const float4*)&Bs[buf][k][rn];
            *(float4*)&b[4] = *(const float4*)&Bs[buf][k][rn+4];
            #pragma unroll
            for (int i = 0; i < 8; i++)
                #pragma unroll
                for (int j = 0; j < 8; j++)
                    acc[i][j] += a[i] * b[j];
        }
        if (more) {
            int nb = buf ^ 1;
            #pragma unroll
            for (int i = 0; i < 2; i++) {
                int row = arow + i * 64;
                As[nb][ak+0][row] = pa[i].x; As[nb][ak+1][row] = pa[i].y;
                As[nb][ak+2][row] = pa[i].z; As[nb][ak+3][row] = pa[i].w;
                *(float4*)&Bs[nb][brow + i*8][bcol] = pb[i];
            }
            __syncthreads();
            buf = nb;
        }
    }

    float bv[8];
    #pragma unroll
    for (int j = 0; j < 8; j++) bv[j] = bias[bn + rn + j];

    #pragma unroll
    for (int i = 0; i < 8; i++) {
        const int m = bm + rm + i;
        float4 v0, v1;
        v0.x = acc[i][0] + bv[0]; v0.y = acc[i][1] + bv[1];
        v0.z = acc[i][2] + bv[2]; v0.w = acc[i][3] + bv[3];
        v1.x = acc[i][4] + bv[4]; v1.y = acc[i][5] + bv[5];
        v1.z = acc[i][6] + bv[6]; v1.w = acc[i][7] + bv[7];
        if (SPLIT == 0) {
            float* Cp = C + (size_t)m * N + bn + rn;
            *(float4*)Cp = v0; *(float4*)(Cp + 4) = v1;
        } else {
            const int b = m >> 11, s = m & (SEQ - 1);
            const int n = bn + rn;
            const int h = n >> 6, d = n & 63;
            float* Cp = C + (((size_t)(b*HEADS + h) * SEQ) + s) * HDIM + d;
            *(float4*)Cp = v0; *(float4*)(Cp + 4) = v1;
        }
    }
}

// ---------------------------------------------------------------------------
// Flash-attention (fp32): one block per (b*h, q-tile of 64). 256 threads.
// Thread t handles q-row r=t/4; score k-cols j = cg+4*jj; out dims c0..c0+15.
// ---------------------------------------------------------------------------
__global__ void __launch_bounds__(256)
attn_kernel()
{
    extern __shared__ float sm[];
    float (*Qs)[68] = (float(*)[68])(sm);
    float (*Ks)[68] = (float(*)[68])(sm + 64*68);
    float (*Vs)[68] = (float(*)[68])(sm + 2*64*68);
    float (*Ps)[68] = (float(*)[68])(sm + 3*64*68);

    const int tid = threadIdx.x;
    const int bh = blockIdx.y;     // 0..31
    const int qt = blockIdx.x;     // 0..31
    const int r  = tid >> 2;       // 0..63
    const int cg = tid & 3;        // 0..3
    const int c0 = cg * 16;

    const float* Qp = g_Q + ((size_t)bh * SEQ + qt*64) * HDIM;
    const float* Kp = g_K + (size_t)bh * SEQ * HDIM;
    const float* Vp = g_V + (size_t)bh * SEQ * HDIM;

    #pragma unroll
    for (int i = 0; i < 4; i++) {
        int id = tid + i * 256;
        int row = id >> 4, c4 = (id & 15) * 4;
        float4 v = *(const float4*)(Qp + (size_t)row * HDIM + c4);
        v.x *= 0.125f; v.y *= 0.125f; v.z *= 0.125f; v.w *= 0.125f; // 1/sqrt(64)
        *(float4*)&Qs[row][c4] = v;
    }

    float o[16];
    #pragma unroll
    for (int i = 0; i < 16; i++) o[i] = 0.f;
    float mi = -1e30f, li = 0.f;

    for (int kt = 0; kt < SEQ/64; kt++) {
        __syncthreads();  // Qs ready (first iter); prev AV done before K/V overwrite
        #pragma unroll
        for (int i = 0; i < 4; i++) {
            int id = tid + i * 256;
            int row = id >> 4, c4 = (id & 15) * 4;
            *(float4*)&Ks[row][c4] = *(const float4*)(Kp + (size_t)(kt*64+row)*HDIM + c4);
            *(float4*)&Vs[row][c4] = *(const float4*)(Vp + (size_t)(kt*64+row)*HDIM + c4);
        }
        __syncthreads();

        // scores s[jj] for k-col j = cg + 4*jj  (bank-conflict-free row spread)
        float s[16];
        #pragma unroll
        for (int jj = 0; jj < 16; jj++) s[jj] = 0.f;
        #pragma unroll
        for (int d4 = 0; d4 < 16; d4++) {
            float4 q = *(const float4*)&Qs[r][d4*4];
            #pragma unroll
            for (int jj = 0; jj < 16; jj++) {
                float4 kv = *(const float4*)&Ks[cg + 4*jj][d4*4];
                s[jj] += q.x*kv.x + q.y*kv.y + q.z*kv.z + q.w*kv.w;
            }
        }

        float m = s[0];
        #pragma unroll
        for (int jj = 1; jj < 16; jj++) m = fmaxf(m, s[jj]);
        m = fmaxf(m, __shfl_xor_sync(0xffffffffu, m, 1));
        m = fmaxf(m, __shfl_xor_sync(0xffffffffu, m, 2));
        const float mnew = fmaxf(mi, m);
        const float corr = __expf(mi - mnew);
        float lsum = 0.f;
        #pragma unroll
        for (int jj = 0; jj < 16; jj++) {
            float p = __expf(s[jj] - mnew);
            Ps[r][cg + 4*jj] = p;
            lsum += p;
        }
        lsum += __shfl_xor_sync(0xffffffffu, lsum, 1);
        lsum += __shfl_xor_sync(0xffffffffu, lsum, 2);
        li = li * corr + lsum;
        mi = mnew;
        #pragma unroll
        for (int i = 0; i < 16; i++) o[i] *= corr;
        __syncwarp();   // Ps row r written by lanes 4r..4r+3 of this warp

        #pragma unroll 8
        for (int j = 0; j < 64; j++) {
            float p = Ps[r][j];
            float4 v0 = *(const float4*)&Vs[j][c0];
            float4 v1 = *(const float4*)&Vs[j][c0+4];
            float4 v2 = *(const float4*)&Vs[j][c0+8];
            float4 v3 = *(const float4*)&Vs[j][c0+12];
            o[0]  += p*v0.x; o[1]  += p*v0.y; o[2]  += p*v0.z; o[3]  += p*v0.w;
            o[4]  += p*v1.x; o[5]  += p*v1.y; o[6]  += p*v1.z; o[7]  += p*v1.w;
            o[8]  += p*v2.x; o[9]  += p*v2.y; o[10] += p*v2.z; o[11] += p*v2.w;
            o[12] += p*v3.x; o[13] += p*v3.y; o[14] += p*v3.z; o[15] += p*v3.w;
        }
    }

    const float inv = 1.f / li;
    const int b = bh >> 4, h = bh & 15;
    float* Op = g_A + ((size_t)(b * SEQ) + qt*64 + r) * EMBED + h*64 + c0;
    #pragma unroll
    for (int i = 0; i < 16; i += 4) {
        float4 v = { o[i]*inv, o[i+1]*inv, o[i+2]*inv, o[i+3]*inv };
        *(float4*)(Op + i) = v;
    }
}

// ---------------------------------------------------------------------------
extern "C" void kernel_launch(void* const* d_in, const int* in_sizes, int n_in,
                              void* d_out, int out_size)
{
    const float* x  = (const float*)d_in[0];
    const float* Wq = (const float*)d_in[1];
    const float* bq = (const float*)d_in[2];
    const float* Wk = (const float*)d_in[3];
    const float* bk = (const float*)d_in[4];
    const float* Wv = (const float*)d_in[5];
    const float* bv = (const float*)d_in[6];
    const float* Wo = (const float*)d_in[7];
    const float* bo = (const float*)d_in[8];
    float* out = (float*)d_out;

    const dim3 gg(EMBED/128, MTOT/128);   // (8, 32)

    sgemm_bias<1><<<gg, 256>>>(x, Wq, bq, nullptr, 0, 1);
    sgemm_bias<1><<<gg, 256>>>(x, Wk, bk, nullptr, 0, 2);
    sgemm_bias<1><<<gg, 256>>>(x, Wv, bv, nullptr, 0, 3);

    const int smem = 4 * 64 * 68 * (int)sizeof(float);  // 69632 B
    cudaFuncSetAttribute(attn_kernel, cudaFuncAttributeMaxDynamicSharedMemorySize, smem);
    attn_kernel<<<dim3(SEQ/64, BATCH*HEADS), 256, smem>>>();

    sgemm_bias<0><<<gg, 256>>>(nullptr, Wo, bo, out, 1, 0);
}

// round 8
// speedup vs baseline: 1.6598x; 1.6598x over previous
#include <cuda_runtime.h>
#include <cuda_bf16.h>
#include <cstdint>

#define EMBED 1024
#define HEADS 16
#define HDIM  64
#define BATCH 2
#define SEQ   2048
#define MTOT  (BATCH*SEQ)   // 4096

using bf16 = __nv_bfloat16;

// ---------------- scratch (static device globals; allocation-free) ----------
__device__ float g_Q[(size_t)BATCH*HEADS*SEQ*HDIM];   // [B,H,S,D]
__device__ float g_K[(size_t)BATCH*HEADS*SEQ*HDIM];
__device__ float g_V[(size_t)BATCH*HEADS*SEQ*HDIM];

__device__ bf16 g_xhi[(size_t)MTOT*EMBED];
__device__ bf16 g_xlo[(size_t)MTOT*EMBED];
__device__ bf16 g_ahi[(size_t)MTOT*EMBED];            // attn out hi/lo (fused)
__device__ bf16 g_alo[(size_t)MTOT*EMBED];
__device__ bf16 g_Wthi[(size_t)4*EMBED*EMBED];        // W^T [N][K], 4 mats
__device__ bf16 g_Wtlo[(size_t)4*EMBED*EMBED];

// ---------------- PTX helpers (baseline sm_103 features only) ---------------
__device__ __forceinline__ uint32_t smem_u32(const void* p) {
    uint32_t a;
    asm("{ .reg .u64 t; cvta.to.shared.u64 t, %1; cvt.u32.u64 %0, t; }" : "=r"(a) : "l"(p));
    return a;
}
__device__ __forceinline__ void cp16(uint32_t s, const void* g) {
    asm volatile("cp.async.cg.shared.global [%0], [%1], 16;" :: "r"(s), "l"(g));
}
__device__ __forceinline__ void cp_commit() {
    asm volatile("cp.async.commit_group;" ::: "memory");
}
template<int N> __device__ __forceinline__ void cp_wait() {
    asm volatile("cp.async.wait_group %0;" :: "n"(N) : "memory");
}
__device__ __forceinline__ void ldsm4(uint32_t a, uint32_t& r0, uint32_t& r1,
                                      uint32_t& r2, uint32_t& r3) {
    asm volatile("ldmatrix.sync.aligned.m8n8.x4.shared.b16 {%0,%1,%2,%3}, [%4];"
                 : "=r"(r0), "=r"(r1), "=r"(r2), "=r"(r3) : "r"(a));
}
__device__ __forceinline__ void ldsm2(uint32_t a, uint32_t& r0, uint32_t& r1) {
    asm volatile("ldmatrix.sync.aligned.m8n8.x2.shared.b16 {%0,%1}, [%2];"
                 : "=r"(r0), "=r"(r1) : "r"(a));
}
__device__ __forceinline__ void mma16816(float* c, const uint32_t* a, const uint32_t* b) {
    asm volatile(
        "mma.sync.aligned.m16n8k16.row.col.f32.bf16.bf16.f32 "
        "{%0,%1,%2,%3}, {%4,%5,%6,%7}, {%8,%9}, {%0,%1,%2,%3};"
        : "+f"(c[0]), "+f"(c[1]), "+f"(c[2]), "+f"(c[3])
        : "r"(a[0]), "r"(a[1]), "r"(a[2]), "r"(a[3]), "r"(b[0]), "r"(b[1]));
}

// ---------------- conversion kernels ---------------------------------------
__global__ void split_x(const float* __restrict__ in)
{
    int i = (blockIdx.x * blockDim.x + threadIdx.x) * 4;
    float4 v = *(const float4*)(in + i);
    bf16 h0 = __float2bfloat16_rn(v.x);
    bf16 h1 = __float2bfloat16_rn(v.y);
    bf16 h2 = __float2bfloat16_rn(v.z);
    bf16 h3 = __float2bfloat16_rn(v.w);
    __nv_bfloat162 hA; hA.x = h0; hA.y = h1;
    __nv_bfloat162 hB; hB.x = h2; hB.y = h3;
    *(__nv_bfloat162*)(g_xhi + i)     = hA;
    *(__nv_bfloat162*)(g_xhi + i + 2) = hB;
    __nv_bfloat162 lA, lB;
    lA.x = __float2bfloat16_rn(v.x - __bfloat162float(h0));
    lA.y = __float2bfloat16_rn(v.y - __bfloat162float(h1));
    lB.x = __float2bfloat16_rn(v.z - __bfloat162float(h2));
    lB.y = __float2bfloat16_rn(v.w - __bfloat162float(h3));
    *(__nv_bfloat162*)(g_xlo + i)     = lA;
    *(__nv_bfloat162*)(g_xlo + i + 2) = lB;
}

// W [K][N] fp32 -> g_Wthi/g_Wtlo[widx] [N][K] bf16 (transpose + hi/lo split)
__global__ void transpose_split(const float* __restrict__ W, int widx)
{
    __shared__ float tile[32][33];
    bf16* Thi = g_Wthi + (size_t)widx * EMBED * EMBED;
    bf16* Tlo = g_Wtlo + (size_t)widx * EMBED * EMBED;
    const int bn = blockIdx.x * 32;
    const int bk = blockIdx.y * 32;
    const int tx = threadIdx.x, ty = threadIdx.y;   // (32, 8)
    #pragma unroll
    for (int i = 0; i < 4; i++)
        tile[ty + i * 8][tx] = W[(size_t)(bk + ty + i * 8) * EMBED + bn + tx];
    __syncthreads();
    #pragma unroll
    for (int i = 0; i < 4; i++) {
        float v = tile[tx][ty + i * 8];
        bf16 h = __float2bfloat16_rn(v);
        bf16 l = __float2bfloat16_rn(v - __bfloat162float(h));
        size_t off = (size_t)(bn + ty + i * 8) * EMBED + bk + tx;
        Thi[off] = h;
        Tlo[off] = l;
    }
}

// ---------------- mma.sync bf16 GEMM (hi/lo 3-pass) --------------------------
// C[4096,1024] = (Ahi+Alo)@(Bhi+Blo)^T + bias  (drop lo*lo)
// CTA 128x128, BK=32, 8 warps (2m x 4n), warp tile 64x32, cp.async dbl-buffer.
#define ASTR 40                      // padded row stride (elems)
#define STAGE_B (128*ASTR*2)         // 10240 B per operand stage

__global__ void __launch_bounds__(256, 2)
mma_gemm(int asel, int widx, const float* __restrict__ bias,
         float* __restrict__ Cext, int csel)
{
    extern __shared__ __align__(128) char smem[];
    char* sAc = smem;
    char* sBc = smem + 2 * STAGE_B;
    float* bias_s = (float*)(smem + 4 * STAGE_B);
    const uint32_t sAu = smem_u32(sAc);
    const uint32_t sBu = smem_u32(sBc);

    const bf16* Ahi = asel ? g_ahi : g_xhi;
    const bf16* Alo = asel ? g_alo : g_xlo;
    const bf16* Bthi = g_Wthi + (size_t)widx * EMBED * EMBED;
    const bf16* Btlo = g_Wtlo + (size_t)widx * EMBED * EMBED;

    const int tid = threadIdx.x, wid = tid >> 5, lane = tid & 31;
    const int bn = blockIdx.x * 128, bm = blockIdx.y * 128;
    const int wm = (wid >> 2) * 64, wn = (wid & 3) * 32;

    if (tid < 128) bias_s[tid] = bias[bn + tid];

    float acc[4][4][4];
    #pragma unroll
    for (int mi = 0; mi < 4; mi++)
        #pragma unroll
        for (int ni = 0; ni < 4; ni++)
            #pragma unroll
            for (int c = 0; c < 4; c++) acc[mi][ni][c] = 0.f;

    auto load_stage = [&](int s, int buf) {
        const int pass = s >> 5;
        const int koff = (s & 31) * 32;
        const bf16* As = (pass == 2) ? Alo : Ahi;
        const bf16* Bs = (pass == 1) ? Btlo : Bthi;
        #pragma unroll
        for (int i = 0; i < 2; i++) {
            int idx = tid * 2 + i;              // 0..511
            int row = idx >> 2, kc = idx & 3;
            cp16(sAu + buf * STAGE_B + (row * ASTR + kc * 8) * 2,
                 As + (size_t)(bm + row) * EMBED + koff + kc * 8);
            cp16(sBu + buf * STAGE_B + (row * ASTR + kc * 8) * 2,
                 Bs + (size_t)(bn + row) * EMBED + koff + kc * 8);
        }
        cp_commit();
    };

    load_stage(0, 0);
    for (int s = 0; s < 96; s++) {
        const int buf = s & 1;
        if (s + 1 < 96) { load_stage(s + 1, buf ^ 1); cp_wait<1>(); }
        else           { cp_wait<0>(); }
        __syncthreads();

        #pragma unroll
        for (int k = 0; k < 32; k += 16) {
            uint32_t a[4][4], b[4][2];
            #pragma unroll
            for (int mi = 0; mi < 4; mi++) {
                int row = wm + mi * 16 + (lane & 15);
                int col = k + 8 * (lane >> 4);
                ldsm4(sAu + buf * STAGE_B + (row * ASTR + col) * 2,
                      a[mi][0], a[mi][1], a[mi][2], a[mi][3]);
            }
            #pragma unroll
            for (int ni = 0; ni < 4; ni++) {
                int row = wn + ni * 8 + (lane & 7);
                int col = k + 8 * ((lane >> 3) & 1);
                ldsm2(sBu + buf * STAGE_B + (row * ASTR + col) * 2,
                      b[ni][0], b[ni][1]);
            }
            #pragma unroll
            for (int mi = 0; mi < 4; mi++)
                #pragma unroll
                for (int ni = 0; ni < 4; ni++)
                    mma16816(acc[mi][ni], a[mi], b[ni]);
        }
        __syncthreads();
    }

    // epilogue: c0/c1 at (row, col..col+1), c2/c3 at (row+8, ...)
    float* C;
    switch (csel) {
        case 1: C = g_Q; break;
        case 2: C = g_K; break;
        case 3: C = g_V; break;
        default: C = Cext; break;
    }
    const int lr = lane >> 2, lc = (lane & 3) * 2;
    #pragma unroll
    for (int mi = 0; mi < 4; mi++) {
        #pragma unroll
        for (int ni = 0; ni < 4; ni++) {
            const int col = bn + wn + ni * 8 + lc;
            const float b0 = bias_s[wn + ni * 8 + lc];
            const float b1 = bias_s[wn + ni * 8 + lc + 1];
            #pragma unroll
            for (int half = 0; half < 2; half++) {
                const int m = bm + wm + mi * 16 + lr + half * 8;
                float2 v;
                v.x = acc[mi][ni][half * 2 + 0] + b0;
                v.y = acc[mi][ni][half * 2 + 1] + b1;
                if (csel != 0) {
                    const int bb = m >> 11, sq = m & (SEQ - 1);
                    const int h = col >> 6, d = col & 63;
                    *(float2*)(C + (((size_t)(bb * HEADS + h) * SEQ) + sq) * HDIM + d) = v;
                } else {
                    *(float2*)(C + (size_t)m * EMBED + col) = v;
                }
            }
        }
    }
}

// ---------------------------------------------------------------------------
// Flash-attention (fp32), 2 q-rows per thread: Q-tile 128, KV-tile 64.
// Thread t: rows r=t>>2 and r+64; score cols j=cg+4*jj; out dims c0..c0+15.
// Epilogue writes bf16 hi/lo directly into g_ahi/g_alo.
// ---------------------------------------------------------------------------
__global__ void __launch_bounds__(256)
attn_kernel()
{
    extern __shared__ float sm[];
    float (*Qs)[68] = (float(*)[68])(sm);               // 128 rows
    float (*Ks)[68] = (float(*)[68])(sm + 128*68);      // 64 rows
    float (*Vs)[68] = (float(*)[68])(sm + 192*68);      // 64 rows
    float (*Ps)[68] = (float(*)[68])(sm + 256*68);      // 128 rows

    const int tid = threadIdx.x;
    const int bh = blockIdx.y;     // 0..31
    const int qt = blockIdx.x;     // 0..15
    const int r  = tid >> 2;       // 0..63
    const int cg = tid & 3;
    const int c0 = cg * 16;

    const float* Qp = g_Q + ((size_t)bh * SEQ + qt*128) * HDIM;
    const float* Kp = g_K + (size_t)bh * SEQ * HDIM;
    const float* Vp = g_V + (size_t)bh * SEQ * HDIM;

    #pragma unroll
    for (int i = 0; i < 8; i++) {
        int id = tid + i * 256;
        int row = id >> 4, c4 = (id & 15) * 4;
        float4 v = *(const float4*)(Qp + (size_t)row * HDIM + c4);
        v.x *= 0.125f; v.y *= 0.125f; v.z *= 0.125f; v.w *= 0.125f; // 1/sqrt(64)
        *(float4*)&Qs[row][c4] = v;
    }

    float o0[16], o1[16];
    #pragma unroll
    for (int i = 0; i < 16; i++) { o0[i] = 0.f; o1[i] = 0.f; }
    float m0 = -1e30f, l0 = 0.f, m1 = -1e30f, l1 = 0.f;

    for (int kt = 0; kt < SEQ/64; kt++) {
        __syncthreads();
        #pragma unroll
        for (int i = 0; i < 4; i++) {
            int id = tid + i * 256;
            int row = id >> 4, c4 = (id & 15) * 4;
            *(float4*)&Ks[row][c4] = *(const float4*)(Kp + (size_t)(kt*64+row)*HDIM + c4);
            *(float4*)&Vs[row][c4] = *(const float4*)(Vp + (size_t)(kt*64+row)*HDIM + c4);
        }
        __syncthreads();

        float s0[16], s1[16];
        #pragma unroll
        for (int jj = 0; jj < 16; jj++) { s0[jj] = 0.f; s1[jj] = 0.f; }
        #pragma unroll
        for (int d4 = 0; d4 < 16; d4++) {
            float4 qa = *(const float4*)&Qs[r][d4*4];
            float4 qb = *(const float4*)&Qs[r+64][d4*4];
            #pragma unroll
            for (int jj = 0; jj < 16; jj++) {
                float4 kv = *(const float4*)&Ks[cg + 4*jj][d4*4];
                s0[jj] += qa.x*kv.x + qa.y*kv.y + qa.z*kv.z + qa.w*kv.w;
                s1[jj] += qb.x*kv.x + qb.y*kv.y + qb.z*kv.z + qb.w*kv.w;
            }
        }

        // online softmax, row r
        {
            float m = s0[0];
            #pragma unroll
            for (int jj = 1; jj < 16; jj++) m = fmaxf(m, s0[jj]);
            m = fmaxf(m, __shfl_xor_sync(0xffffffffu, m, 1));
            m = fmaxf(m, __shfl_xor_sync(0xffffffffu, m, 2));
            const float mnew = fmaxf(m0, m);
            const float corr = __expf(m0 - mnew);
            float lsum = 0.f;
            #pragma unroll
            for (int jj = 0; jj < 16; jj++) {
                float p = __expf(s0[jj] - mnew);
                Ps[r][cg + 4*jj] = p;
                lsum += p;
            }
            lsum += __shfl_xor_sync(0xffffffffu, lsum, 1);
            lsum += __shfl_xor_sync(0xffffffffu, lsum, 2);
            l0 = l0 * corr + lsum;
            m0 = mnew;
            #pragma unroll
            for (int i = 0; i < 16; i++) o0[i] *= corr;
        }
        // online softmax, row r+64
        {
            float m = s1[0];
            #pragma unroll
            for (int jj = 1; jj < 16; jj++) m = fmaxf(m, s1[jj]);
            m = fmaxf(m, __shfl_xor_sync(0xffffffffu, m, 1));
            m = fmaxf(m, __shfl_xor_sync(0xffffffffu, m, 2));
            const float mnew = fmaxf(m1, m);
            const float corr = __expf(m1 - mnew);
            float lsum = 0.f;
            #pragma unroll
            for (int jj = 0; jj < 16; jj++) {
                float p = __expf(s1[jj] - mnew);
                Ps[r+64][cg + 4*jj] = p;
                lsum += p;
            }
            lsum += __shfl_xor_sync(0xffffffffu, lsum, 1);
            lsum += __shfl_xor_sync(0xffffffffu, lsum, 2);
            l1 = l1 * corr + lsum;
            m1 = mnew;
            #pragma unroll
            for (int i = 0; i < 16; i++) o1[i] *= corr;
        }
        __syncwarp();   // Ps rows r / r+64 written by lanes of this warp only

        #pragma unroll 4
        for (int j = 0; j < 64; j++) {
            float p0 = Ps[r][j];
            float p1 = Ps[r+64][j];
            float4 v0 = *(const float4*)&Vs[j][c0];
            float4 v1 = *(const float4*)&Vs[j][c0+4];
            float4 v2 = *(const float4*)&Vs[j][c0+8];
            float4 v3 = *(const float4*)&Vs[j][c0+12];
            o0[0]  += p0*v0.x; o0[1]  += p0*v0.y; o0[2]  += p0*v0.z; o0[3]  += p0*v0.w;
            o0[4]  += p0*v1.x; o0[5]  += p0*v1.y; o0[6]  += p0*v1.z; o0[7]  += p0*v1.w;
            o0[8]  += p0*v2.x; o0[9]  += p0*v2.y; o0[10] += p0*v2.z; o0[11] += p0*v2.w;
            o0[12] += p0*v3.x; o0[13] += p0*v3.y; o0[14] += p0*v3.z; o0[15] += p0*v3.w;
            o1[0]  += p1*v0.x; o1[1]  += p1*v0.y; o1[2]  += p1*v0.z; o1[3]  += p1*v0.w;
            o1[4]  += p1*v1.x; o1[5]  += p1*v1.y; o1[6]  += p1*v1.z; o1[7]  += p1*v1.w;
            o1[8]  += p1*v2.x; o1[9]  += p1*v2.y; o1[10] += p1*v2.z; o1[11] += p1*v2.w;
            o1[12] += p1*v3.x; o1[13] += p1*v3.y; o1[14] += p1*v3.z; o1[15] += p1*v3.w;
        }
    }

    const float inv0 = 1.f / l0;
    const float inv1 = 1.f / l1;
    const int b = bh >> 4, h = bh & 15;
    const size_t base0 = ((size_t)(b * SEQ) + qt*128 + r) * EMBED + h*64 + c0;
    const size_t base1 = base0 + (size_t)64 * EMBED;
    #pragma unroll
    for (int i = 0; i < 16; i += 2) {
        float va = o0[i] * inv0, vb = o0[i+1] * inv0;
        bf16 ha = __float2bfloat16_rn(va), hb = __float2bfloat16_rn(vb);
        __nv_bfloat162 hp; hp.x = ha; hp.y = hb;
        *(__nv_bfloat162*)(g_ahi + base0 + i) = hp;
        __nv_bfloat162 lp;
        lp.x = __float2bfloat16_rn(va - __bfloat162float(ha));
        lp.y = __float2bfloat16_rn(vb - __bfloat162float(hb));
        *(__nv_bfloat162*)(g_alo + base0 + i) = lp;

        va = o1[i] * inv1; vb = o1[i+1] * inv1;
        ha = __float2bfloat16_rn(va); hb = __float2bfloat16_rn(vb);
        hp.x = ha; hp.y = hb;
        *(__nv_bfloat162*)(g_ahi + base1 + i) = hp;
        lp.x = __float2bfloat16_rn(va - __bfloat162float(ha));
        lp.y = __float2bfloat16_rn(vb - __bfloat162float(hb));
        *(__nv_bfloat162*)(g_alo + base1 + i) = lp;
    }
}

// ---------------------------------------------------------------------------
extern "C" void kernel_launch(void* const* d_in, const int* in_sizes, int n_in,
                              void* d_out, int out_size)
{
    const float* x  = (const float*)d_in[0];
    const float* Wq = (const float*)d_in[1];
    const float* bq = (const float*)d_in[2];
    const float* Wk = (const float*)d_in[3];
    const float* bk = (const float*)d_in[4];
    const float* Wv = (const float*)d_in[5];
    const float* bv = (const float*)d_in[6];
    const float* Wo = (const float*)d_in[7];
    const float* bo = (const float*)d_in[8];
    float* out = (float*)d_out;

    const int gsm = 4 * STAGE_B + 512;                  // 41472 B
    const int asm_sz = 384 * 68 * (int)sizeof(float);   // 104448 B
    cudaFuncSetAttribute(mma_gemm, cudaFuncAttributeMaxDynamicSharedMemorySize, gsm);
    cudaFuncSetAttribute(attn_kernel, cudaFuncAttributeMaxDynamicSharedMemorySize, asm_sz);

    const int NTOT = MTOT * EMBED;
    split_x<<<NTOT / 4 / 256, 256>>>(x);

    const dim3 tb(32, 8), tg(EMBED / 32, EMBED / 32);
    transpose_split<<<tg, tb>>>(Wq, 0);
    transpose_split<<<tg, tb>>>(Wk, 1);
    transpose_split<<<tg, tb>>>(Wv, 2);
    transpose_split<<<tg, tb>>>(Wo, 3);

    const dim3 gg(EMBED / 128, MTOT / 128);   // (8, 32)
    mma_gemm<<<gg, 256, gsm>>>(0, 0, bq, nullptr, 1);
    mma_gemm<<<gg, 256, gsm>>>(0, 1, bk, nullptr, 2);
    mma_gemm<<<gg, 256, gsm>>>(0, 2, bv, nullptr, 3);

    attn_kernel<<<dim3(SEQ/128, BATCH*HEADS), 256, asm_sz>>>();

    mma_gemm<<<gg, 256, gsm>>>(1, 3, bo, out, 0);
}

// round 9
// speedup vs baseline: 4.4722x; 2.6944x over previous
#include <cuda_runtime.h>
#include <cuda_bf16.h>
#include <cstdint>

#define EMBED 1024
#define HEADS 16
#define HDIM  64
#define BATCH 2
#define SEQ   2048
#define MTOT  (BATCH*SEQ)   // 4096

using bf16 = __nv_bfloat16;

// ---------------- scratch (static device globals; allocation-free) ----------
__device__ bf16 g_Qhi[(size_t)BATCH*HEADS*SEQ*HDIM];   // [BH,S,D] bf16 hi/lo
__device__ bf16 g_Qlo[(size_t)BATCH*HEADS*SEQ*HDIM];
__device__ bf16 g_Khi[(size_t)BATCH*HEADS*SEQ*HDIM];
__device__ bf16 g_Klo[(size_t)BATCH*HEADS*SEQ*HDIM];
__device__ bf16 g_Vhi[(size_t)BATCH*HEADS*SEQ*HDIM];
__device__ bf16 g_Vlo[(size_t)BATCH*HEADS*SEQ*HDIM];

__device__ bf16 g_xhi[(size_t)MTOT*EMBED];
__device__ bf16 g_xlo[(size_t)MTOT*EMBED];
__device__ bf16 g_ahi[(size_t)MTOT*EMBED];            // attn out hi/lo (fused)
__device__ bf16 g_alo[(size_t)MTOT*EMBED];
__device__ bf16 g_Wthi[(size_t)4*EMBED*EMBED];        // W^T [N][K], 4 mats
__device__ bf16 g_Wtlo[(size_t)4*EMBED*EMBED];

// ---------------- PTX helpers (baseline sm_103 features only) ---------------
__device__ __forceinline__ uint32_t smem_u32(const void* p) {
    uint32_t a;
    asm("{ .reg .u64 t; cvta.to.shared.u64 t, %1; cvt.u32.u64 %0, t; }" : "=r"(a) : "l"(p));
    return a;
}
__device__ __forceinline__ void cp16(uint32_t s, const void* g) {
    asm volatile("cp.async.cg.shared.global [%0], [%1], 16;" :: "r"(s), "l"(g));
}
__device__ __forceinline__ void cp_commit() {
    asm volatile("cp.async.commit_group;" ::: "memory");
}
template<int N> __device__ __forceinline__ void cp_wait() {
    asm volatile("cp.async.wait_group %0;" :: "n"(N) : "memory");
}
__device__ __forceinline__ void ldsm4(uint32_t a, uint32_t& r0, uint32_t& r1,
                                      uint32_t& r2, uint32_t& r3) {
    asm volatile("ldmatrix.sync.aligned.m8n8.x4.shared.b16 {%0,%1,%2,%3}, [%4];"
                 : "=r"(r0), "=r"(r1), "=r"(r2), "=r"(r3) : "r"(a));
}
__device__ __forceinline__ void ldsm4t(uint32_t a, uint32_t& r0, uint32_t& r1,
                                       uint32_t& r2, uint32_t& r3) {
    asm volatile("ldmatrix.sync.aligned.m8n8.x4.trans.shared.b16 {%0,%1,%2,%3}, [%4];"
                 : "=r"(r0), "=r"(r1), "=r"(r2), "=r"(r3) : "r"(a));
}
__device__ __forceinline__ void ldsm2(uint32_t a, uint32_t& r0, uint32_t& r1) {
    asm volatile("ldmatrix.sync.aligned.m8n8.x2.shared.b16 {%0,%1}, [%2];"
                 : "=r"(r0), "=r"(r1) : "r"(a));
}
__device__ __forceinline__ void mma16816(float* c, const uint32_t* a, const uint32_t* b) {
    asm volatile(
        "mma.sync.aligned.m16n8k16.row.col.f32.bf16.bf16.f32 "
        "{%0,%1,%2,%3}, {%4,%5,%6,%7}, {%8,%9}, {%0,%1,%2,%3};"
        : "+f"(c[0]), "+f"(c[1]), "+f"(c[2]), "+f"(c[3])
        : "r"(a[0]), "r"(a[1]), "r"(a[2]), "r"(a[3]), "r"(b[0]), "r"(b[1]));
}
// pack (e0,e1) -> bf16x2 hi + residual bf16x2 lo  (e0 in low half)
__device__ __forceinline__ void split2(float e0, float e1, uint32_t& hi, uint32_t& lo) {
    asm("cvt.rn.bf16x2.f32 %0, %1, %2;" : "=r"(hi) : "f"(e1), "f"(e0));
    float f0 = __uint_as_float(hi << 16);
    float f1 = __uint_as_float(hi & 0xFFFF0000u);
    float l0 = e0 - f0, l1 = e1 - f1;
    asm("cvt.rn.bf16x2.f32 %0, %1, %2;" : "=r"(lo) : "f"(l1), "f"(l0));
}

// ---------------- conversion kernels ---------------------------------------
__global__ void split_x(const float* __restrict__ in)
{
    int i = (blockIdx.x * blockDim.x + threadIdx.x) * 4;
    float4 v = *(const float4*)(in + i);
    uint32_t h0, l0, h1, l1;
    split2(v.x, v.y, h0, l0);
    split2(v.z, v.w, h1, l1);
    *(uint32_t*)(g_xhi + i)     = h0;
    *(uint32_t*)(g_xhi + i + 2) = h1;
    *(uint32_t*)(g_xlo + i)     = l0;
    *(uint32_t*)(g_xlo + i + 2) = l1;
}

// W [K][N] fp32 -> g_Wthi/g_Wtlo[widx] [N][K] bf16 (transpose + hi/lo split)
__global__ void transpose_split(const float* __restrict__ W, int widx)
{
    __shared__ float tile[32][33];
    bf16* Thi = g_Wthi + (size_t)widx * EMBED * EMBED;
    bf16* Tlo = g_Wtlo + (size_t)widx * EMBED * EMBED;
    const int bn = blockIdx.x * 32;
    const int bk = blockIdx.y * 32;
    const int tx = threadIdx.x, ty = threadIdx.y;   // (32, 8)
    #pragma unroll
    for (int i = 0; i < 4; i++)
        tile[ty + i * 8][tx] = W[(size_t)(bk + ty + i * 8) * EMBED + bn + tx];
    __syncthreads();
    #pragma unroll
    for (int i = 0; i < 4; i++) {
        float v = tile[tx][ty + i * 8];
        bf16 h = __float2bfloat16_rn(v);
        bf16 l = __float2bfloat16_rn(v - __bfloat162float(h));
        size_t off = (size_t)(bn + ty + i * 8) * EMBED + bk + tx;
        Thi[off] = h;
        Tlo[off] = l;
    }
}

// ---------------- mma.sync bf16 GEMM (hi/lo 3-pass) --------------------------
#define ASTR 40                      // padded row stride (elems)
#define STAGE_B (128*ASTR*2)         // 10240 B per operand stage

__global__ void __launch_bounds__(256, 2)
mma_gemm(int asel, int widx, const float* __restrict__ bias,
         float* __restrict__ Cext, int csel)
{
    extern __shared__ __align__(128) char smem[];
    float* bias_s = (float*)(smem + 4 * STAGE_B);
    const uint32_t sAu = smem_u32(smem);
    const uint32_t sBu = sAu + 2 * STAGE_B;

    const bf16* Ahi = asel ? g_ahi : g_xhi;
    const bf16* Alo = asel ? g_alo : g_xlo;
    const bf16* Bthi = g_Wthi + (size_t)widx * EMBED * EMBED;
    const bf16* Btlo = g_Wtlo + (size_t)widx * EMBED * EMBED;

    const int tid = threadIdx.x, wid = tid >> 5, lane = tid & 31;
    const int bn = blockIdx.x * 128, bm = blockIdx.y * 128;
    const int wm = (wid >> 2) * 64, wn = (wid & 3) * 32;

    if (tid < 128) bias_s[tid] = bias[bn + tid];

    float acc[4][4][4];
    #pragma unroll
    for (int mi = 0; mi < 4; mi++)
        #pragma unroll
        for (int ni = 0; ni < 4; ni++)
            #pragma unroll
            for (int c = 0; c < 4; c++) acc[mi][ni][c] = 0.f;

    auto load_stage = [&](int s, int buf) {
        const int pass = s >> 5;
        const int koff = (s & 31) * 32;
        const bf16* As = (pass == 2) ? Alo : Ahi;
        const bf16* Bs = (pass == 1) ? Btlo : Bthi;
        #pragma unroll
        for (int i = 0; i < 2; i++) {
            int idx = tid * 2 + i;
            int row = idx >> 2, kc = idx & 3;
            cp16(sAu + buf * STAGE_B + (row * ASTR + kc * 8) * 2,
                 As + (size_t)(bm + row) * EMBED + koff + kc * 8);
            cp16(sBu + buf * STAGE_B + (row * ASTR + kc * 8) * 2,
                 Bs + (size_t)(bn + row) * EMBED + koff + kc * 8);
        }
        cp_commit();
    };

    load_stage(0, 0);
    for (int s = 0; s < 96; s++) {
        const int buf = s & 1;
        if (s + 1 < 96) { load_stage(s + 1, buf ^ 1); cp_wait<1>(); }
        else           { cp_wait<0>(); }
        __syncthreads();

        #pragma unroll
        for (int k = 0; k < 32; k += 16) {
            uint32_t a[4][4], b[4][2];
            #pragma unroll
            for (int mi = 0; mi < 4; mi++) {
                int row = wm + mi * 16 + (lane & 15);
                int col = k + 8 * (lane >> 4);
                ldsm4(sAu + buf * STAGE_B + (row * ASTR + col) * 2,
                      a[mi][0], a[mi][1], a[mi][2], a[mi][3]);
            }
            #pragma unroll
            for (int ni = 0; ni < 4; ni++) {
                int row = wn + ni * 8 + (lane & 7);
                int col = k + 8 * ((lane >> 3) & 1);
                ldsm2(sBu + buf * STAGE_B + (row * ASTR + col) * 2,
                      b[ni][0], b[ni][1]);
            }
            #pragma unroll
            for (int mi = 0; mi < 4; mi++)
                #pragma unroll
                for (int ni = 0; ni < 4; ni++)
                    mma16816(acc[mi][ni], a[mi], b[ni]);
        }
        __syncthreads();
    }

    const int lr = lane >> 2, lc = (lane & 3) * 2;
    if (csel != 0) {
        bf16 *Chi, *Clo;
        if (csel == 1)      { Chi = g_Qhi; Clo = g_Qlo; }
        else if (csel == 2) { Chi = g_Khi; Clo = g_Klo; }
        else                { Chi = g_Vhi; Clo = g_Vlo; }
        #pragma unroll
        for (int mi = 0; mi < 4; mi++) {
            #pragma unroll
            for (int ni = 0; ni < 4; ni++) {
                const int col = bn + wn + ni * 8 + lc;
                const float b0 = bias_s[wn + ni * 8 + lc];
                const float b1 = bias_s[wn + ni * 8 + lc + 1];
                const int h = col >> 6, d = col & 63;
                #pragma unroll
                for (int half = 0; half < 2; half++) {
                    const int m = bm + wm + mi * 16 + lr + half * 8;
                    const int bb = m >> 11, sq = m & (SEQ - 1);
                    uint32_t hi2, lo2;
                    split2(acc[mi][ni][half * 2 + 0] + b0,
                           acc[mi][ni][half * 2 + 1] + b1, hi2, lo2);
                    size_t off = (((size_t)(bb * HEADS + h) * SEQ) + sq) * HDIM + d;
                    *(uint32_t*)(Chi + off) = hi2;
                    *(uint32_t*)(Clo + off) = lo2;
                }
            }
        }
    } else {
        #pragma unroll
        for (int mi = 0; mi < 4; mi++) {
            #pragma unroll
            for (int ni = 0; ni < 4; ni++) {
                const int col = bn + wn + ni * 8 + lc;
                const float b0 = bias_s[wn + ni * 8 + lc];
                const float b1 = bias_s[wn + ni * 8 + lc + 1];
                #pragma unroll
                for (int half = 0; half < 2; half++) {
                    const int m = bm + wm + mi * 16 + lr + half * 8;
                    float2 v;
                    v.x = acc[mi][ni][half * 2 + 0] + b0;
                    v.y = acc[mi][ni][half * 2 + 1] + b1;
                    *(float2*)(Cext + (size_t)m * EMBED + col) = v;
                }
            }
        }
    }
}

// ---------------------------------------------------------------------------
// Tensor-core flash attention. Q-tile 128 (8 warps x 16 rows), KV-tile 64.
// S = (Qhi+Qlo)(Khi+Klo)^T   3-pass hi/lo mma
// O += (Phi+Plo)(Vhi+Vlo)    3-pass, P kept in registers (S-frag == A-frag)
// ---------------------------------------------------------------------------
#define ROWB  144                 // padded row stride bytes (72 bf16)
#define QSZ   (128*ROWB)          // 18432 B per Q array
#define KVARR (64*ROWB)           // 9216 B per KV array
#define KVSTG (4*KVARR)           // 36864 B per stage (Khi,Klo,Vhi,Vlo)
#define ATTN_SMEM (2*QSZ + 2*KVSTG)   // 110592 B

__global__ void __launch_bounds__(256)
attn_mma()
{
    extern __shared__ __align__(128) char smem[];
    const uint32_t uQ  = smem_u32(smem);          // Qhi, then Qlo at +QSZ
    const uint32_t uKV = uQ + 2 * QSZ;

    const int tid = threadIdx.x;
    const int w = tid >> 5, lane = tid & 31;
    const int qt = blockIdx.x;      // 0..15
    const int bh = blockIdx.y;      // 0..31
    const int b = bh >> 4, h = bh & 15;

    const bf16* gQh = g_Qhi + ((size_t)bh * SEQ + qt * 128) * HDIM;
    const bf16* gQl = g_Qlo + ((size_t)bh * SEQ + qt * 128) * HDIM;
    const bf16* gKh = g_Khi + (size_t)bh * SEQ * HDIM;
    const bf16* gKl = g_Klo + (size_t)bh * SEQ * HDIM;
    const bf16* gVh = g_Vhi + (size_t)bh * SEQ * HDIM;
    const bf16* gVl = g_Vlo + (size_t)bh * SEQ * HDIM;

    // ---- prologue: Q (group 0) ----
    #pragma unroll
    for (int i = 0; i < 8; i++) {
        int c = tid + i * 256;            // 0..2047
        int arr = c >> 10, rem = c & 1023;
        int row = rem >> 3, c8 = rem & 7;
        const bf16* g = (arr ? gQl : gQh) + row * HDIM + c8 * 8;
        cp16(uQ + arr * QSZ + row * ROWB + c8 * 16, g);
    }
    cp_commit();

    auto load_kv = [&](int kt, int buf) {
        #pragma unroll
        for (int i = 0; i < 8; i++) {
            int c = tid + i * 256;        // 0..2047
            int arr = c >> 9, rem = c & 511;
            int row = rem >> 3, c8 = rem & 7;
            const bf16* g = (arr < 2) ? (arr ? gKl : gKh) : ((arr == 2) ? gVh : gVl);
            cp16(uKV + buf * KVSTG + arr * KVARR + row * ROWB + c8 * 16,
                 g + (size_t)(kt * 64 + row) * HDIM + c8 * 8);
        }
        cp_commit();
    };

    load_kv(0, 0);
    cp_wait<1>();        // Q ready (tile0 still in flight)
    __syncthreads();

    // ---- preload Q fragments (constant across kv loop) ----
    uint32_t qh[4][4], ql[4][4];
    #pragma unroll
    for (int kb = 0; kb < 4; kb++) {
        uint32_t a = uQ + (w * 16 + (lane & 15)) * ROWB + kb * 32 + (lane >> 4) * 16;
        ldsm4(a, qh[kb][0], qh[kb][1], qh[kb][2], qh[kb][3]);
        ldsm4(a + QSZ, ql[kb][0], ql[kb][1], ql[kb][2], ql[kb][3]);
    }

    float o[8][4];
    #pragma unroll
    for (int ni = 0; ni < 8; ni++)
        #pragma unroll
        for (int c = 0; c < 4; c++) o[ni][c] = 0.f;
    float mrow[2] = { -1e30f, -1e30f };
    float lrow[2] = { 0.f, 0.f };

    for (int kt = 0; kt < SEQ / 64; kt++) {
        const int buf = kt & 1;
        __syncthreads();                       // prev compute done everywhere
        if (kt + 1 < SEQ / 64) { load_kv(kt + 1, buf ^ 1); cp_wait<1>(); }
        else                   { cp_wait<0>(); }
        __syncthreads();

        const uint32_t kHi = uKV + buf * KVSTG;
        const uint32_t kLo = kHi + KVARR;
        const uint32_t vHi = kHi + 2 * KVARR;
        const uint32_t vLo = kHi + 3 * KVARR;

        // ---- S = Q K^T (3-pass) ----
        float s[8][4];
        #pragma unroll
        for (int ni = 0; ni < 8; ni++)
            #pragma unroll
            for (int c = 0; c < 4; c++) s[ni][c] = 0.f;

        #pragma unroll
        for (int kb = 0; kb < 4; kb++) {
            uint32_t bk[4][4];
            const uint32_t nofs = (lane & 7) + (lane >> 4) * 8;
            const uint32_t kofs = kb * 32 + ((lane >> 3) & 1) * 16;
            #pragma unroll
            for (int nb = 0; nb < 4; nb++)
                ldsm4(kHi + (nb * 16 + nofs) * ROWB + kofs,
                      bk[nb][0], bk[nb][1], bk[nb][2], bk[nb][3]);
            #pragma unroll
            for (int nb = 0; nb < 4; nb++) {
                mma16816(s[2*nb],   qh[kb], &bk[nb][0]);
                mma16816(s[2*nb+1], qh[kb], &bk[nb][2]);
                mma16816(s[2*nb],   ql[kb], &bk[nb][0]);
                mma16816(s[2*nb+1], ql[kb], &bk[nb][2]);
            }
            #pragma unroll
            for (int nb = 0; nb < 4; nb++)
                ldsm4(kLo + (nb * 16 + nofs) * ROWB + kofs,
                      bk[nb][0], bk[nb][1], bk[nb][2], bk[nb][3]);
            #pragma unroll
            for (int nb = 0; nb < 4; nb++) {
                mma16816(s[2*nb],   qh[kb], &bk[nb][0]);
                mma16816(s[2*nb+1], qh[kb], &bk[nb][2]);
            }
        }

        // ---- online softmax (warp-local; rows lr & lr+8) ----
        #pragma unroll
        for (int ni = 0; ni < 8; ni++)
            #pragma unroll
            for (int c = 0; c < 4; c++) s[ni][c] *= 0.125f;   // 1/sqrt(64)

        #pragma unroll
        for (int hf = 0; hf < 2; hf++) {
            float rm = s[0][2*hf];
            #pragma unroll
            for (int ni = 0; ni < 8; ni++) {
                rm = fmaxf(rm, s[ni][2*hf]);
                rm = fmaxf(rm, s[ni][2*hf+1]);
            }
            rm = fmaxf(rm, __shfl_xor_sync(0xffffffffu, rm, 1));
            rm = fmaxf(rm, __shfl_xor_sync(0xffffffffu, rm, 2));
            const float mnew = fmaxf(mrow[hf], rm);
            const float corr = __expf(mrow[hf] - mnew);
            mrow[hf] = mnew;
            float rs = 0.f;
            #pragma unroll
            for (int ni = 0; ni < 8; ni++) {
                float p0 = __expf(s[ni][2*hf]   - mnew);
                float p1 = __expf(s[ni][2*hf+1] - mnew);
                s[ni][2*hf] = p0; s[ni][2*hf+1] = p1;
                rs += p0 + p1;
            }
            rs += __shfl_xor_sync(0xffffffffu, rs, 1);
            rs += __shfl_xor_sync(0xffffffffu, rs, 2);
            lrow[hf] = lrow[hf] * corr + rs;
            #pragma unroll
            for (int ni = 0; ni < 8; ni++) {
                o[ni][2*hf]   *= corr;
                o[ni][2*hf+1] *= corr;
            }
        }

        // ---- pack P into A-fragments (hi + residual lo), no smem ----
        uint32_t ph[4][4], pl[4][4];
        #pragma unroll
        for (int kb = 0; kb < 4; kb++) {
            split2(s[2*kb][0],   s[2*kb][1],   ph[kb][0], pl[kb][0]);
            split2(s[2*kb][2],   s[2*kb][3],   ph[kb][1], pl[kb][1]);
            split2(s[2*kb+1][0], s[2*kb+1][1], ph[kb][2], pl[kb][2]);
            split2(s[2*kb+1][2], s[2*kb+1][3], ph[kb][3], pl[kb][3]);
        }

        // ---- O += P V (3-pass) ----
        #pragma unroll
        for (int kb = 0; kb < 4; kb++) {
            uint32_t bv[4][4];
            const uint32_t krow = kb * 16 + (lane & 7) + ((lane >> 3) & 1) * 8;
            const uint32_t ncol = (lane >> 4) * 16;
            #pragma unroll
            for (int nb = 0; nb < 4; nb++)
                ldsm4t(vHi + krow * ROWB + nb * 32 + ncol,
                       bv[nb][0], bv[nb][1], bv[nb][2], bv[nb][3]);
            #pragma unroll
            for (int nb = 0; nb < 4; nb++) {
                mma16816(o[2*nb],   ph[kb], &bv[nb][0]);
                mma16816(o[2*nb+1], ph[kb], &bv[nb][2]);
                mma16816(o[2*nb],   pl[kb], &bv[nb][0]);
                mma16816(o[2*nb+1], pl[kb], &bv[nb][2]);
            }
            #pragma unroll
            for (int nb = 0; nb < 4; nb++)
                ldsm4t(vLo + krow * ROWB + nb * 32 + ncol,
                       bv[nb][0], bv[nb][1], bv[nb][2], bv[nb][3]);
            #pragma unroll
            for (int nb = 0; nb < 4; nb++) {
                mma16816(o[2*nb],   ph[kb], &bv[nb][0]);
                mma16816(o[2*nb+1], ph[kb], &bv[nb][2]);
            }
        }
    }

    // ---- epilogue: normalize, hi/lo split, store to g_ahi/g_alo ----
    const float inv0 = 1.f / lrow[0];
    const float inv1 = 1.f / lrow[1];
    const int lr = lane >> 2, lc = (lane & 3) * 2;
    const size_t r0 = ((size_t)b * SEQ + qt * 128 + w * 16 + lr) * EMBED + h * 64;
    const size_t r1 = r0 + (size_t)8 * EMBED;
    #pragma unroll
    for (int ni = 0; ni < 8; ni++) {
        const int d = ni * 8 + lc;
        uint32_t hi2, lo2;
        split2(o[ni][0] * inv0, o[ni][1] * inv0, hi2, lo2);
        *(uint32_t*)(g_ahi + r0 + d) = hi2;
        *(uint32_t*)(g_alo + r0 + d) = lo2;
        split2(o[ni][2] * inv1, o[ni][3] * inv1, hi2, lo2);
        *(uint32_t*)(g_ahi + r1 + d) = hi2;
        *(uint32_t*)(g_alo + r1 + d) = lo2;
    }
}

// ---------------------------------------------------------------------------
extern "C" void kernel_launch(void* const* d_in, const int* in_sizes, int n_in,
                              void* d_out, int out_size)
{
    const float* x  = (const float*)d_in[0];
    const float* Wq = (const float*)d_in[1];
    const float* bq = (const float*)d_in[2];
    const float* Wk = (const float*)d_in[3];
    const float* bk = (const float*)d_in[4];
    const float* Wv = (const float*)d_in[5];
    const float* bv = (const float*)d_in[6];
    const float* Wo = (const float*)d_in[7];
    const float* bo = (const float*)d_in[8];
    float* out = (float*)d_out;

    const int gsm = 4 * STAGE_B + 512;                  // 41472 B
    cudaFuncSetAttribute(mma_gemm, cudaFuncAttributeMaxDynamicSharedMemorySize, gsm);
    cudaFuncSetAttribute(attn_mma, cudaFuncAttributeMaxDynamicSharedMemorySize, ATTN_SMEM);

    const int NTOT = MTOT * EMBED;
    split_x<<<NTOT / 4 / 256, 256>>>(x);

    const dim3 tb(32, 8), tg(EMBED / 32, EMBED / 32);
    transpose_split<<<tg, tb>>>(Wq, 0);
    transpose_split<<<tg, tb>>>(Wk, 1);
    transpose_split<<<tg, tb>>>(Wv, 2);
    transpose_split<<<tg, tb>>>(Wo, 3);

    const dim3 gg(EMBED / 128, MTOT / 128);   // (8, 32)
    mma_gemm<<<gg, 256, gsm>>>(0, 0, bq, nullptr, 1);
    mma_gemm<<<gg, 256, gsm>>>(0, 1, bk, nullptr, 2);
    mma_gemm<<<gg, 256, gsm>>>(0, 2, bv, nullptr, 3);

    attn_mma<<<dim3(SEQ / 128, BATCH * HEADS), 256, ATTN_SMEM>>>();

    mma_gemm<<<gg, 256, gsm>>>(1, 3, bo, out, 0);
}

// round 13
// speedup vs baseline: 5.3875x; 1.2047x over previous
#include <cuda_runtime.h>
#include <cuda_bf16.h>
#include <cstdint>

#define EMBED 1024
#define HEADS 16
#define HDIM  64
#define BATCH 2
#define SEQ   2048
#define MTOT  (BATCH*SEQ)   // 4096

using bf16 = __nv_bfloat16;

// ---------------- scratch (static device globals; allocation-free) ----------
__device__ bf16 g_Qhi[(size_t)BATCH*HEADS*SEQ*HDIM];   // [BH,S,D] bf16 hi/lo
__device__ bf16 g_Qlo[(size_t)BATCH*HEADS*SEQ*HDIM];
__device__ bf16 g_Khi[(size_t)BATCH*HEADS*SEQ*HDIM];
__device__ bf16 g_Klo[(size_t)BATCH*HEADS*SEQ*HDIM];
__device__ bf16 g_Vhi[(size_t)BATCH*HEADS*SEQ*HDIM];
__device__ bf16 g_Vlo[(size_t)BATCH*HEADS*SEQ*HDIM];

__device__ bf16 g_xhi[(size_t)MTOT*EMBED];
__device__ bf16 g_xlo[(size_t)MTOT*EMBED];
__device__ bf16 g_ahi[(size_t)MTOT*EMBED];            // attn out hi/lo (fused)
__device__ bf16 g_alo[(size_t)MTOT*EMBED];
__device__ bf16 g_Wthi[(size_t)4*EMBED*EMBED];        // W^T [N][K], 4 mats
__device__ bf16 g_Wtlo[(size_t)4*EMBED*EMBED];

// ---------------- PTX helpers (baseline sm_103 features only) ---------------
__device__ __forceinline__ uint32_t smem_u32(const void* p) {
    uint32_t a;
    asm("{ .reg .u64 t; cvta.to.shared.u64 t, %1; cvt.u32.u64 %0, t; }" : "=r"(a) : "l"(p));
    return a;
}
__device__ __forceinline__ void cp16(uint32_t s, const void* g) {
    asm volatile("cp.async.cg.shared.global [%0], [%1], 16;" :: "r"(s), "l"(g));
}
__device__ __forceinline__ void cp_commit() {
    asm volatile("cp.async.commit_group;" ::: "memory");
}
template<int N> __device__ __forceinline__ void cp_wait() {
    asm volatile("cp.async.wait_group %0;" :: "n"(N) : "memory");
}
__device__ __forceinline__ void ldsm4(uint32_t a, uint32_t& r0, uint32_t& r1,
                                      uint32_t& r2, uint32_t& r3) {
    asm volatile("ldmatrix.sync.aligned.m8n8.x4.shared.b16 {%0,%1,%2,%3}, [%4];"
                 : "=r"(r0), "=r"(r1), "=r"(r2), "=r"(r3) : "r"(a));
}
__device__ __forceinline__ void ldsm4t(uint32_t a, uint32_t& r0, uint32_t& r1,
                                       uint32_t& r2, uint32_t& r3) {
    asm volatile("ldmatrix.sync.aligned.m8n8.x4.trans.shared.b16 {%0,%1,%2,%3}, [%4];"
                 : "=r"(r0), "=r"(r1), "=r"(r2), "=r"(r3) : "r"(a));
}
__device__ __forceinline__ void mma16816(float* c, const uint32_t* a, const uint32_t* b) {
    asm volatile(
        "mma.sync.aligned.m16n8k16.row.col.f32.bf16.bf16.f32 "
        "{%0,%1,%2,%3}, {%4,%5,%6,%7}, {%8,%9}, {%0,%1,%2,%3};"
        : "+f"(c[0]), "+f"(c[1]), "+f"(c[2]), "+f"(c[3])
        : "r"(a[0]), "r"(a[1]), "r"(a[2]), "r"(a[3]), "r"(b[0]), "r"(b[1]));
}
// pack (e0,e1) -> bf16x2 hi + residual bf16x2 lo  (e0 in low half)
__device__ __forceinline__ void split2(float e0, float e1, uint32_t& hi, uint32_t& lo) {
    asm("cvt.rn.bf16x2.f32 %0, %1, %2;" : "=r"(hi) : "f"(e1), "f"(e0));
    float f0 = __uint_as_float(hi << 16);
    float f1 = __uint_as_float(hi & 0xFFFF0000u);
    float l0 = e0 - f0, l1 = e1 - f1;
    asm("cvt.rn.bf16x2.f32 %0, %1, %2;" : "=r"(lo) : "f"(l1), "f"(l0));
}

// ---------------- conversion kernels ---------------------------------------
__global__ void split_x(const float* __restrict__ in)
{
    int i = (blockIdx.x * blockDim.x + threadIdx.x) * 4;
    float4 v = *(const float4*)(in + i);
    uint32_t h0, l0, h1, l1;
    split2(v.x, v.y, h0, l0);
    split2(v.z, v.w, h1, l1);
    *(uint32_t*)(g_xhi + i)     = h0;
    *(uint32_t*)(g_xhi + i + 2) = h1;
    *(uint32_t*)(g_xlo + i)     = l0;
    *(uint32_t*)(g_xlo + i + 2) = l1;
}

// W [K][N] fp32 -> g_Wthi/g_Wtlo[widx] [N][K] bf16 (transpose + hi/lo split)
__global__ void transpose_split(const float* __restrict__ W, int widx)
{
    __shared__ float tile[32][33];
    bf16* Thi = g_Wthi + (size_t)widx * EMBED * EMBED;
    bf16* Tlo = g_Wtlo + (size_t)widx * EMBED * EMBED;
    const int bn = blockIdx.x * 32;
    const int bk = blockIdx.y * 32;
    const int tx = threadIdx.x, ty = threadIdx.y;   // (32, 8)
    #pragma unroll
    for (int i = 0; i < 4; i++)
        tile[ty + i * 8][tx] = W[(size_t)(bk + ty + i * 8) * EMBED + bn + tx];
    __syncthreads();
    #pragma unroll
    for (int i = 0; i < 4; i++) {
        float v = tile[tx][ty + i * 8];
        bf16 h = __float2bfloat16_rn(v);
        bf16 l = __float2bfloat16_rn(v - __bfloat162float(h));
        size_t off = (size_t)(bn + ty + i * 8) * EMBED + bk + tx;
        Thi[off] = h;
        Tlo[off] = l;
    }
}

// ---------------- mma.sync bf16 GEMM (hi/lo 3-pass) --------------------------
// C[4096,1024] = (Ahi+Alo)@(Bhi+Blo)^T + bias  (drop lo*lo)
// CTA 256x128, BK=64, 8 warps (4m x 2n), warp tile 64x64.
// 3-stage cp.async pipeline, ONE __syncthreads per stage, 48 stages.
#define GROWB 144                     // padded row stride bytes (72 bf16)
#define GA_B  (256*GROWB)             // 36864 B (A tile)
#define GB_B  (128*GROWB)             // 18432 B (B tile)
#define GSTG  (GA_B + GB_B)           // 55296 B per stage
#define GEMM_SMEM (3*GSTG + 512)      // 166400 B

__global__ void __launch_bounds__(256, 1)
mma_gemm(int asel, int widx, const float* __restrict__ bias,
         float* __restrict__ Cext, int csel)
{
    extern __shared__ __align__(128) char smem[];
    float* bias_s = (float*)(smem + 3 * GSTG);
    const uint32_t sb = smem_u32(smem);

    const bf16* Ahi = asel ? g_ahi : g_xhi;
    const bf16* Alo = asel ? g_alo : g_xlo;
    const bf16* Bthi = g_Wthi + (size_t)widx * EMBED * EMBED;
    const bf16* Btlo = g_Wtlo + (size_t)widx * EMBED * EMBED;

    const int tid = threadIdx.x, wid = tid >> 5, lane = tid & 31;
    const int bn = blockIdx.x * 128, bm = blockIdx.y * 256;
    const int wm = (wid >> 1) * 64, wn = (wid & 1) * 64;

    if (tid < 128) bias_s[tid] = bias[bn + tid];

    float acc[4][8][4];
    #pragma unroll
    for (int mi = 0; mi < 4; mi++)
        #pragma unroll
        for (int ni = 0; ni < 8; ni++)
            #pragma unroll
            for (int c = 0; c < 4; c++) acc[mi][ni][c] = 0.f;

    // stage s: pass = s>>4 (0: hi*hi, 1: hi*lo, 2: lo*hi), koff = (s&15)*64
    auto load_stage = [&](int s) {
        const int pass = s >> 4;
        const int koff = (s & 15) * 64;
        const bf16* As = (pass == 2) ? Alo : Ahi;
        const bf16* Bs = (pass == 1) ? Btlo : Bthi;
        const uint32_t base = sb + (s % 3) * GSTG;
        // A: 256 rows x 64 cols = 2048 cp16 -> 8 per thread
        #pragma unroll
        for (int i = 0; i < 8; i++) {
            int idx = tid + i * 256;          // 0..2047
            int row = idx >> 3, c8 = idx & 7;
            cp16(base + row * GROWB + c8 * 16,
                 As + (size_t)(bm + row) * EMBED + koff + c8 * 8);
        }
        // B: 128 rows x 64 cols = 1024 cp16 -> 4 per thread
        #pragma unroll
        for (int i = 0; i < 4; i++) {
            int idx = tid + i * 256;          // 0..1023
            int row = idx >> 3, c8 = idx & 7;
            cp16(base + GA_B + row * GROWB + c8 * 16,
                 Bs + (size_t)(bn + row) * EMBED + koff + c8 * 8);
        }
        cp_commit();
    };

    load_stage(0);
    load_stage(1);

    for (int s = 0; s < 48; s++) {
        if (s == 47) cp_wait<0>(); else cp_wait<1>();
        __syncthreads();
        if (s + 2 < 48) load_stage(s + 2);

        const uint32_t sA = sb + (s % 3) * GSTG;
        const uint32_t sB = sA + GA_B;

        #pragma unroll
        for (int k = 0; k < 64; k += 16) {
            uint32_t a[4][4], b[4][4];
            #pragma unroll
            for (int mi = 0; mi < 4; mi++) {
                uint32_t ad = sA + (wm + mi * 16 + (lane & 15)) * GROWB
                            + k * 2 + (lane >> 4) * 16;
                ldsm4(ad, a[mi][0], a[mi][1], a[mi][2], a[mi][3]);
            }
            #pragma unroll
            for (int nb = 0; nb < 4; nb++) {
                // n16k16 block: lanes 0-7 m0(n0-7,k0-7), 8-15 m1(n0-7,k8-15),
                //               16-23 m2(n8-15,k0-7), 24-31 m3(n8-15,k8-15)
                uint32_t bd = sB + (wn + nb * 16 + (lane & 7) + (lane >> 4) * 8) * GROWB
                            + k * 2 + ((lane >> 3) & 1) * 16;
                ldsm4(bd, b[nb][0], b[nb][1], b[nb][2], b[nb][3]);
            }
            #pragma unroll
            for (int mi = 0; mi < 4; mi++)
                #pragma unroll
                for (int nb = 0; nb < 4; nb++) {
                    mma16816(acc[mi][2*nb],   a[mi], &b[nb][0]);
                    mma16816(acc[mi][2*nb+1], a[mi], &b[nb][2]);
                }
        }
    }
    __syncthreads();

    const int lr = lane >> 2, lc = (lane & 3) * 2;
    if (csel != 0) {
        bf16 *Chi, *Clo;
        if (csel == 1)      { Chi = g_Qhi; Clo = g_Qlo; }
        else if (csel == 2) { Chi = g_Khi; Clo = g_Klo; }
        else                { Chi = g_Vhi; Clo = g_Vlo; }
        #pragma unroll
        for (int mi = 0; mi < 4; mi++) {
            #pragma unroll
            for (int ni = 0; ni < 8; ni++) {
                const int col = bn + wn + ni * 8 + lc;
                const float b0 = bias_s[wn + ni * 8 + lc];
                const float b1 = bias_s[wn + ni * 8 + lc + 1];
                const int h = col >> 6, d = col & 63;
                #pragma unroll
                for (int half = 0; half < 2; half++) {
                    const int m = bm + wm + mi * 16 + lr + half * 8;
                    const int bb = m >> 11, sq = m & (SEQ - 1);
                    uint32_t hi2, lo2;
                    split2(acc[mi][ni][half * 2 + 0] + b0,
                           acc[mi][ni][half * 2 + 1] + b1, hi2, lo2);
                    size_t off = (((size_t)(bb * HEADS + h) * SEQ) + sq) * HDIM + d;
                    *(uint32_t*)(Chi + off) = hi2;
                    *(uint32_t*)(Clo + off) = lo2;
                }
            }
        }
    } else {
        #pragma unroll
        for (int mi = 0; mi < 4; mi++) {
            #pragma unroll
            for (int ni = 0; ni < 8; ni++) {
                const int col = bn + wn + ni * 8 + lc;
                const float b0 = bias_s[wn + ni * 8 + lc];
                const float b1 = bias_s[wn + ni * 8 + lc + 1];
                #pragma unroll
                for (int half = 0; half < 2; half++) {
                    const int m = bm + wm + mi * 16 + lr + half * 8;
                    float2 v;
                    v.x = acc[mi][ni][half * 2 + 0] + b0;
                    v.y = acc[mi][ni][half * 2 + 1] + b1;
                    *(float2*)(Cext + (size_t)m * EMBED + col) = v;
                }
            }
        }
    }
}

// ---------------------------------------------------------------------------
// Tensor-core flash attention (unchanged from Round 9 — proven).
// ---------------------------------------------------------------------------
#define ROWB  144
#define QSZ   (128*ROWB)
#define KVARR (64*ROWB)
#define KVSTG (4*KVARR)
#define ATTN_SMEM (2*QSZ + 2*KVSTG)

__global__ void __launch_bounds__(256)
attn_mma()
{
    extern __shared__ __align__(128) char smem[];
    const uint32_t uQ  = smem_u32(smem);
    const uint32_t uKV = uQ + 2 * QSZ;

    const int tid = threadIdx.x;
    const int w = tid >> 5, lane = tid & 31;
    const int qt = blockIdx.x;
    const int bh = blockIdx.y;
    const int b = bh >> 4, h = bh & 15;

    const bf16* gQh = g_Qhi + ((size_t)bh * SEQ + qt * 128) * HDIM;
    const bf16* gQl = g_Qlo + ((size_t)bh * SEQ + qt * 128) * HDIM;
    const bf16* gKh = g_Khi + (size_t)bh * SEQ * HDIM;
    const bf16* gKl = g_Klo + (size_t)bh * SEQ * HDIM;
    const bf16* gVh = g_Vhi + (size_t)bh * SEQ * HDIM;
    const bf16* gVl = g_Vlo + (size_t)bh * SEQ * HDIM;

    #pragma unroll
    for (int i = 0; i < 8; i++) {
        int c = tid + i * 256;
        int arr = c >> 10, rem = c & 1023;
        int row = rem >> 3, c8 = rem & 7;
        const bf16* g = (arr ? gQl : gQh) + row * HDIM + c8 * 8;
        cp16(uQ + arr * QSZ + row * ROWB + c8 * 16, g);
    }
    cp_commit();

    auto load_kv = [&](int kt, int buf) {
        #pragma unroll
        for (int i = 0; i < 8; i++) {
            int c = tid + i * 256;
            int arr = c >> 9, rem = c & 511;
            int row = rem >> 3, c8 = rem & 7;
            const bf16* g = (arr < 2) ? (arr ? gKl : gKh) : ((arr == 2) ? gVh : gVl);
            cp16(uKV + buf * KVSTG + arr * KVARR + row * ROWB + c8 * 16,
                 g + (size_t)(kt * 64 + row) * HDIM + c8 * 8);
        }
        cp_commit();
    };

    load_kv(0, 0);
    cp_wait<1>();
    __syncthreads();

    uint32_t qh[4][4], ql[4][4];
    #pragma unroll
    for (int kb = 0; kb < 4; kb++) {
        uint32_t a = uQ + (w * 16 + (lane & 15)) * ROWB + kb * 32 + (lane >> 4) * 16;
        ldsm4(a, qh[kb][0], qh[kb][1], qh[kb][2], qh[kb][3]);
        ldsm4(a + QSZ, ql[kb][0], ql[kb][1], ql[kb][2], ql[kb][3]);
    }

    float o[8][4];
    #pragma unroll
    for (int ni = 0; ni < 8; ni++)
        #pragma unroll
        for (int c = 0; c < 4; c++) o[ni][c] = 0.f;
    float mrow[2] = { -1e30f, -1e30f };
    float lrow[2] = { 0.f, 0.f };

    for (int kt = 0; kt < SEQ / 64; kt++) {
        const int buf = kt & 1;
        __syncthreads();
        if (kt + 1 < SEQ / 64) { load_kv(kt + 1, buf ^ 1); cp_wait<1>(); }
        else                   { cp_wait<0>(); }
        __syncthreads();

        const uint32_t kHi = uKV + buf * KVSTG;
        const uint32_t kLo = kHi + KVARR;
        const uint32_t vHi = kHi + 2 * KVARR;
        const uint32_t vLo = kHi + 3 * KVARR;

        float s[8][4];
        #pragma unroll
        for (int ni = 0; ni < 8; ni++)
            #pragma unroll
            for (int c = 0; c < 4; c++) s[ni][c] = 0.f;

        #pragma unroll
        for (int kb = 0; kb < 4; kb++) {
            uint32_t bk[4][4];
            const uint32_t nofs = (lane & 7) + (lane >> 4) * 8;
            const uint32_t kofs = kb * 32 + ((lane >> 3) & 1) * 16;
            #pragma unroll
            for (int nb = 0; nb < 4; nb++)
                ldsm4(kHi + (nb * 16 + nofs) * ROWB + kofs,
                      bk[nb][0], bk[nb][1], bk[nb][2], bk[nb][3]);
            #pragma unroll
            for (int nb = 0; nb < 4; nb++) {
                mma16816(s[2*nb],   qh[kb], &bk[nb][0]);
                mma16816(s[2*nb+1], qh[kb], &bk[nb][2]);
                mma16816(s[2*nb],   ql[kb], &bk[nb][0]);
                mma16816(s[2*nb+1], ql[kb], &bk[nb][2]);
            }
            #pragma unroll
            for (int nb = 0; nb < 4; nb++)
                ldsm4(kLo + (nb * 16 + nofs) * ROWB + kofs,
                      bk[nb][0], bk[nb][1], bk[nb][2], bk[nb][3]);
            #pragma unroll
            for (int nb = 0; nb < 4; nb++) {
                mma16816(s[2*nb],   qh[kb], &bk[nb][0]);
                mma16816(s[2*nb+1], qh[kb], &bk[nb][2]);
            }
        }

        #pragma unroll
        for (int ni = 0; ni < 8; ni++)
            #pragma unroll
            for (int c = 0; c < 4; c++) s[ni][c] *= 0.125f;

        #pragma unroll
        for (int hf = 0; hf < 2; hf++) {
            float rm = s[0][2*hf];
            #pragma unroll
            for (int ni = 0; ni < 8; ni++) {
                rm = fmaxf(rm, s[ni][2*hf]);
                rm = fmaxf(rm, s[ni][2*hf+1]);
            }
            rm = fmaxf(rm, __shfl_xor_sync(0xffffffffu, rm, 1));
            rm = fmaxf(rm, __shfl_xor_sync(0xffffffffu, rm, 2));
            const float mnew = fmaxf(mrow[hf], rm);
            const float corr = __expf(mrow[hf] - mnew);
            mrow[hf] = mnew;
            float rs = 0.f;
            #pragma unroll
            for (int ni = 0; ni < 8; ni++) {
                float p0 = __expf(s[ni][2*hf]   - mnew);
                float p1 = __expf(s[ni][2*hf+1] - mnew);
                s[ni][2*hf] = p0; s[ni][2*hf+1] = p1;
                rs += p0 + p1;
            }
            rs += __shfl_xor_sync(0xffffffffu, rs, 1);
            rs += __shfl_xor_sync(0xffffffffu, rs, 2);
            lrow[hf] = lrow[hf] * corr + rs;
            #pragma unroll
            for (int ni = 0; ni < 8; ni++) {
                o[ni][2*hf]   *= corr;
                o[ni][2*hf+1] *= corr;
            }
        }

        uint32_t ph[4][4], pl[4][4];
        #pragma unroll
        for (int kb = 0; kb < 4; kb++) {
            split2(s[2*kb][0],   s[2*kb][1],   ph[kb][0], pl[kb][0]);
            split2(s[2*kb][2],   s[2*kb][3],   ph[kb][1], pl[kb][1]);
            split2(s[2*kb+1][0], s[2*kb+1][1], ph[kb][2], pl[kb][2]);
            split2(s[2*kb+1][2], s[2*kb+1][3], ph[kb][3], pl[kb][3]);
        }

        #pragma unroll
        for (int kb = 0; kb < 4; kb++) {
            uint32_t bv[4][4];
            const uint32_t krow = kb * 16 + (lane & 7) + ((lane >> 3) & 1) * 8;
            const uint32_t ncol = (lane >> 4) * 16;
            #pragma unroll
            for (int nb = 0; nb < 4; nb++)
                ldsm4t(vHi + krow * ROWB + nb * 32 + ncol,
                       bv[nb][0], bv[nb][1], bv[nb][2], bv[nb][3]);
            #pragma unroll
            for (int nb = 0; nb < 4; nb++) {
                mma16816(o[2*nb],   ph[kb], &bv[nb][0]);
                mma16816(o[2*nb+1], ph[kb], &bv[nb][2]);
                mma16816(o[2*nb],   pl[kb], &bv[nb][0]);
                mma16816(o[2*nb+1], pl[kb], &bv[nb][2]);
            }
            #pragma unroll
            for (int nb = 0; nb < 4; nb++)
                ldsm4t(vLo + krow * ROWB + nb * 32 + ncol,
                       bv[nb][0], bv[nb][1], bv[nb][2], bv[nb][3]);
            #pragma unroll
            for (int nb = 0; nb < 4; nb++) {
                mma16816(o[2*nb],   ph[kb], &bv[nb][0]);
                mma16816(o[2*nb+1], ph[kb], &bv[nb][2]);
            }
        }
    }

    const float inv0 = 1.f / lrow[0];
    const float inv1 = 1.f / lrow[1];
    const int lr = lane >> 2, lc = (lane & 3) * 2;
    const size_t r0 = ((size_t)b * SEQ + qt * 128 + w * 16 + lr) * EMBED + h * 64;
    const size_t r1 = r0 + (size_t)8 * EMBED;
    #pragma unroll
    for (int ni = 0; ni < 8; ni++) {
        const int d = ni * 8 + lc;
        uint32_t hi2, lo2;
        split2(o[ni][0] * inv0, o[ni][1] * inv0, hi2, lo2);
        *(uint32_t*)(g_ahi + r0 + d) = hi2;
        *(uint32_t*)(g_alo + r0 + d) = lo2;
        split2(o[ni][2] * inv1, o[ni][3] * inv1, hi2, lo2);
        *(uint32_t*)(g_ahi + r1 + d) = hi2;
        *(uint32_t*)(g_alo + r1 + d) = lo2;
    }
}

// ---------------------------------------------------------------------------
extern "C" void kernel_launch(void* const* d_in, const int* in_sizes, int n_in,
                              void* d_out, int out_size)
{
    const float* x  = (const float*)d_in[0];
    const float* Wq = (const float*)d_in[1];
    const float* bq = (const float*)d_in[2];
    const float* Wk = (const float*)d_in[3];
    const float* bk = (const float*)d_in[4];
    const float* Wv = (const float*)d_in[5];
    const float* bv = (const float*)d_in[6];
    const float* Wo = (const float*)d_in[7];
    const float* bo = (const float*)d_in[8];
    float* out = (float*)d_out;

    cudaFuncSetAttribute(mma_gemm, cudaFuncAttributeMaxDynamicSharedMemorySize, GEMM_SMEM);
    cudaFuncSetAttribute(attn_mma, cudaFuncAttributeMaxDynamicSharedMemorySize, ATTN_SMEM);

    const int NTOT = MTOT * EMBED;
    split_x<<<NTOT / 4 / 256, 256>>>(x);

    const dim3 tb(32, 8), tg(EMBED / 32, EMBED / 32);
    transpose_split<<<tg, tb>>>(Wq, 0);
    transpose_split<<<tg, tb>>>(Wk, 1);
    transpose_split<<<tg, tb>>>(Wv, 2);
    transpose_split<<<tg, tb>>>(Wo, 3);

    const dim3 gg(EMBED / 128, MTOT / 256);   // (8, 16) = 128 CTAs
    mma_gemm<<<gg, 256, GEMM_SMEM>>>(0, 0, bq, nullptr, 1);
    mma_gemm<<<gg, 256, GEMM_SMEM>>>(0, 1, bk, nullptr, 2);
    mma_gemm<<<gg, 256, GEMM_SMEM>>>(0, 2, bv, nullptr, 3);

    attn_mma<<<dim3(SEQ / 128, BATCH * HEADS), 256, ATTN_SMEM>>>();

    mma_gemm<<<gg, 256, GEMM_SMEM>>>(1, 3, bo, out, 0);
}